// round 15
// baseline (speedup 1.0000x reference)
#include <cuda_runtime.h>
#include <cuda_bf16.h>
#include <cstdint>

// Soft decision tree, DEPTH=8, 32 feats, 10 classes, B=131072.
// P(leaf) = (prod e over right edges) / (prod (1+e) over path), e = exp(x[f]-t).
// Single-wave layout: BT=64, SPB=64, 2-way subtree split (half == warp, only
// the root replicated). 13 blocks/SM -> grid 2048 ~= one wave (6% tail).
// Combined rcp at depth-6; packed d6 float4 records; uint4 leaf class offsets.

#define DEPTH   8
#define N_FEAT  32
#define N_CLS   10
#define BT      64                // threads per block (2 warps = 2 halves)
#define SPB     64                // samples per block (32 pairs)
#define NPAIR   32
#define PADF    66                // padded floats per feature row
#define N_INNER 31                // inner nodes per half subtree (tree depths 1..5)

#define LOG2E 1.4426950408889634f

__device__ __forceinline__ float ex2f(float z) {
    float e; asm("ex2.approx.f32 %0, %1;" : "=f"(e) : "f"(z)); return e;
}
__device__ __forceinline__ float rcpf(float d) {
    float r; asm("rcp.approx.f32 %0, %1;" : "=f"(r) : "f"(d)); return r;
}
__device__ __forceinline__ float2 lds2(const char* p) { return *(const float2*)p; }

// ld = local depth in half-subtree (0..4 plain, 5 = depth-6 handler), j = local idx.
template <int ld, int j>
struct Walk {
    static __device__ __forceinline__ void run(float Na, float Da, float Nb, float Db,
                                               const char* xb, char* sb,
                                               const float2* ps, const float4* d6r,
                                               const uint4* pk) {
        float2 p  = ps[(1 << ld) - 1 + j];              // broadcast LDS.64
        float2 xv = lds2(xb + __float_as_int(p.y));     // pair LDS.64
        float ea = ex2f(fmaf(xv.x, LOG2E, p.x));
        float eb = ex2f(fmaf(xv.y, LOG2E, p.x));
        float Dna = fmaf(Da, ea, Da);                   // D*(1+e)
        float Dnb = fmaf(Db, eb, Db);
        Walk<ld + 1, 2 * j>::run(Na, Dna, Nb, Dnb, xb, sb, ps, d6r, pk);
        Walk<ld + 1, 2 * j + 1>::run(Na * ea, Dna, Nb * eb, Dnb, xb, sb, ps, d6r, pk);
    }
};

// Local depth 5 == tree depth 6: node + both depth-7 children; one rcp per
// sample serves both children: r = rcp(DL*DR); 1/DL = r*DR; 1/DR = r*DL.
// Packed records: r0 = {p6x, off6, pLx, offL}, r1 = {pRx, offR, -, -}.
template <int j>
struct Walk<5, j> {
    static __device__ __forceinline__ void run(float Na, float Da, float Nb, float Db,
                                               const char* xb, char* sb,
                                               const float2* ps, const float4* d6r,
                                               const uint4* pk) {
        float4 r0 = d6r[2 * j];                         // broadcast LDS.128
        float4 r1 = d6r[2 * j + 1];                     // broadcast LDS.128

        float2 x6 = lds2(xb + __float_as_int(r0.y));
        float e6a = ex2f(fmaf(x6.x, LOG2E, r0.x));
        float e6b = ex2f(fmaf(x6.y, LOG2E, r0.x));
        float D6a = fmaf(Da, e6a, Da);
        float D6b = fmaf(Db, e6b, Db);
        float NRa = Na * e6a;
        float NRb = Nb * e6b;

        float2 xL = lds2(xb + __float_as_int(r0.w));
        float eLa = ex2f(fmaf(xL.x, LOG2E, r0.z));
        float eLb = ex2f(fmaf(xL.y, LOG2E, r0.z));
        float DLa = fmaf(D6a, eLa, D6a);
        float DLb = fmaf(D6b, eLb, D6b);

        float2 xR = lds2(xb + __float_as_int(r1.y));
        float eRa = ex2f(fmaf(xR.x, LOG2E, r1.x));
        float eRb = ex2f(fmaf(xR.y, LOG2E, r1.x));
        float DRa = fmaf(D6a, eRa, D6a);
        float DRb = fmaf(D6b, eRb, D6b);

        float ra  = rcpf(DLa * DRa);
        float rb  = rcpf(DLb * DRb);
        float iLa = ra * DRa, iRa = ra * DLa;
        float iLb = rb * DRb, iRb = rb * DLb;

        float PLLa = Na * iLa,   PLLb = Nb * iLb;       // leaf 4j
        float PLRa = PLLa * eLa, PLRb = PLLb * eLb;     // leaf 4j+1
        float PRLa = NRa * iRa,  PRLb = NRb * iRb;      // leaf 4j+2
        float PRRa = PRLa * eRa, PRRb = PRLb * eRb;     // leaf 4j+3

        uint4 k = pk[j];                                // broadcast LDS.128
        {
            float2* a = (float2*)(sb + k.x);
            float2 v = *a; v.x += PLLa; v.y += PLLb; *a = v;
        }
        {
            float2* a = (float2*)(sb + k.y);
            float2 v = *a; v.x += PLRa; v.y += PLRb; *a = v;
        }
        {
            float2* a = (float2*)(sb + k.z);
            float2 v = *a; v.x += PRLa; v.y += PRLb; *a = v;
        }
        {
            float2* a = (float2*)(sb + k.w);
            float2 v = *a; v.x += PRRa; v.y += PRRb; *a = v;
        }
    }
};

__global__ void __launch_bounds__(BT, 13)
dt_kernel(const float* __restrict__ x,
          const float* __restrict__ thr,
          const int*   __restrict__ feats,
          const int*   __restrict__ cls,
          float* __restrict__ out) {
    __shared__ __align__(16) float    xs[N_FEAT * PADF];      // 8.25 KB
    __shared__ __align__(16) float    sacc[2 * N_CLS * SPB];  // 5.0 KB
    __shared__ __align__(8)  float2   s_top[1];               // root
    __shared__ __align__(8)  float2   s_ps[2 * N_INNER];      // 496 B (depths 1..5)
    __shared__ __align__(16) float4   s_d6[64 * 2];           // 2 KB (d6+d7 params)
    __shared__ __align__(16) uint4    s_pk[64];               // 1 KB leaf offsets

    const int tid = threadIdx.x;
    const int bs  = blockIdx.x * SPB;
    const int h   = tid >> 5;              // half == warp index
    const int pr  = tid & (NPAIR - 1);     // sample-pair index (lane)

    // ---- per-block param prep ----
    if (tid == 0) {
        s_top[0] = make_float2(-thr[0] * LOG2E, __int_as_float(feats[0] * PADF * 4));
    }
    if (tid < 2 * N_INNER) {               // 62 inner params (tree depths 1..5)
        int hh  = tid / N_INNER;
        int rem = tid - hh * N_INNER;      // 0..30, level order within half
        int ldp = 31 - __clz(rem + 1);     // 0..4 -> tree depth ldp+1
        int j   = rem + 1 - (1 << ldp);
        int g   = ((1 << (ldp + 1)) - 1) + hh * (1 << ldp) + j;
        s_ps[tid] = make_float2(-thr[g] * LOG2E, __int_as_float(feats[g] * PADF * 4));
    }
#pragma unroll
    for (int rd = 0; rd < 2; rd++) {       // 128 float4 d6 records
        int i = tid + rd * BT;             // 0..127
        int m = i >> 1;                    // global in-level d6 index 0..63
        int w = i & 1;
        if (w == 0) {
            int g6 = 63 + m;               // depth-6 node
            int gL = 127 + 2 * m;          // left d7 child
            s_d6[i] = make_float4(-thr[g6] * LOG2E,
                                  __int_as_float(feats[g6] * PADF * 4),
                                  -thr[gL] * LOG2E,
                                  __int_as_float(feats[gL] * PADF * 4));
        } else {
            int gR = 128 + 2 * m;          // right d7 child
            s_d6[i] = make_float4(-thr[gR] * LOG2E,
                                  __int_as_float(feats[gR] * PADF * 4),
                                  0.f, 0.f);
        }
    }
    {                                      // leaf class byte-offsets per d6
        int lb = tid * 4;
        s_pk[tid] = make_uint4((uint32_t)cls[lb + 0] * (SPB * 4),
                               (uint32_t)cls[lb + 1] * (SPB * 4),
                               (uint32_t)cls[lb + 2] * (SPB * 4),
                               (uint32_t)cls[lb + 3] * (SPB * 4));
    }

    // ---- stage 64 samples x 32 feats, coalesced LDG.128 ----
#pragma unroll
    for (int k = 0; k < (SPB * N_FEAT / 4) / BT; k++) {   // 8 iterations
        int idx = tid + k * BT;
        int s   = idx >> 3;
        int c4  = idx & 7;
        float4 v = reinterpret_cast<const float4*>(x + (size_t)(bs + s) * N_FEAT)[c4];
        xs[(c4 * 4 + 0) * PADF + s] = v.x;
        xs[(c4 * 4 + 1) * PADF + s] = v.y;
        xs[(c4 * 4 + 2) * PADF + s] = v.z;
        xs[(c4 * 4 + 3) * PADF + s] = v.w;
    }

    char* sb = (char*)sacc + h * (N_CLS * SPB * 4) + 8 * pr;
#pragma unroll
    for (int c = 0; c < N_CLS; c++)
        *(float2*)(sb + c * (SPB * 4)) = make_float2(0.f, 0.f);

    __syncthreads();

    const char* xb = (const char*)xs + 8 * pr;
    const float2* ps  = s_ps + h * N_INNER;
    const float4* d6r = s_d6 + h * 64;     // 32 d6 records x2 per half
    const uint4*  pk  = s_pk + h * 32;

    // replicated root
    float2 p0  = s_top[0];
    float2 xv0 = lds2(xb + __float_as_int(p0.y));
    float e0a = ex2f(fmaf(xv0.x, LOG2E, p0.x));
    float e0b = ex2f(fmaf(xv0.y, LOG2E, p0.x));
    float Da = e0a + 1.f;
    float Db = e0b + 1.f;
    float Na = h ? e0a : 1.0f;
    float Nb = h ? e0b : 1.0f;

    Walk<0, 0>::run(Na, Da, Nb, Db, xb, sb, ps, d6r, pk);

    __syncthreads();

    // combine 2 half-accumulators, write out (thread t -> sample t)
    {
        float a[N_CLS];
#pragma unroll
        for (int c = 0; c < N_CLS; c++) {
            a[c] = sacc[c * SPB + tid] + sacc[N_CLS * SPB + c * SPB + tid];
        }
        float* o = out + (size_t)(bs + tid) * N_CLS;
#pragma unroll
        for (int c = 0; c < N_CLS; c += 2)
            *(float2*)(o + c) = make_float2(a[c], a[c + 1]);
    }
}

extern "C" void kernel_launch(void* const* d_in, const int* in_sizes, int n_in,
                              void* d_out, int out_size) {
    const float* x     = (const float*)d_in[0];
    const float* thr   = (const float*)d_in[1];
    const int*   feats = (const int*)d_in[2];
    const int*   cls   = (const int*)d_in[3];
    float*       out   = (float*)d_out;

    const int B = in_sizes[0] / N_FEAT;

    dt_kernel<<<B / SPB, BT>>>(x, thr, feats, cls, out);
}

// round 16
// speedup vs baseline: 1.7135x; 1.7135x over previous
#include <cuda_runtime.h>
#include <cuda_bf16.h>
#include <cstdint>

// Soft decision tree, DEPTH=8, 32 feats, 10 classes, B=131072.
// P(leaf) = (prod e over right edges) / (prod (1+e) over path), e = exp(x[f]-t).
// KEY: exp(x[f]-t) = exp(x[f]) * exp(-t). Shared holds E[f,s] = exp(x[f,s])
// (32 ex2/sample in staging); each node eval is ONE FMUL (e = E*c with
// c = exp(-t) pre-transformed). R14 skeleton: BT=128, 2 samples/thread,
// 4-way subtree split (quarter==warp), combined rcp at depth-6, packed d6
// records, uint4 leaf class offsets.

#define DEPTH   8
#define N_FEAT  32
#define N_CLS   10
#define BT      128               // threads per block
#define SPB     64                // samples per block (32 pairs x 4 quarter-warps)
#define NPAIR   32
#define PADF    66                // padded floats per feature row
#define N_INNER 15                // inner nodes per quarter subtree (depths 2..5)

#define LOG2E 1.4426950408889634f

__device__ __forceinline__ float ex2f(float z) {
    float e; asm("ex2.approx.f32 %0, %1;" : "=f"(e) : "f"(z)); return e;
}
__device__ __forceinline__ float rcpf(float d) {
    float r; asm("rcp.approx.f32 %0, %1;" : "=f"(r) : "f"(d)); return r;
}
__device__ __forceinline__ float2 lds2(const char* p) { return *(const float2*)p; }

// ld = local depth (0..3 plain, 4 = depth-6 handler), j = local node index.
// Node eval: e = E[f] * c  (one FMUL per sample; no MUFU in the tree walk
// except the combined rcp at depth-6).
template <int ld, int j>
struct Walk {
    static __device__ __forceinline__ void run(float Na, float Da, float Nb, float Db,
                                               const char* xb, char* sb,
                                               const float2* ps, const float4* d6r,
                                               const uint4* pk) {
        float2 p  = ps[(1 << ld) - 1 + j];              // broadcast LDS.64: {c, off}
        float2 xv = lds2(xb + __float_as_int(p.y));     // pair LDS.64: {E_a, E_b}
        float ea = xv.x * p.x;
        float eb = xv.y * p.x;
        float Dna = fmaf(Da, ea, Da);                   // D*(1+e)
        float Dnb = fmaf(Db, eb, Db);
        Walk<ld + 1, 2 * j>::run(Na, Dna, Nb, Dnb, xb, sb, ps, d6r, pk);
        Walk<ld + 1, 2 * j + 1>::run(Na * ea, Dna, Nb * eb, Dnb, xb, sb, ps, d6r, pk);
    }
};

// Depth-6 handler: node + both depth-7 children; one rcp per sample serves
// both children: r = rcp(DL*DR); 1/DL = r*DR; 1/DR = r*DL.
// Packed records: r0 = {c6, off6, cL, offL}, r1 = {cR, offR, -, -}.
template <int j>
struct Walk<4, j> {
    static __device__ __forceinline__ void run(float Na, float Da, float Nb, float Db,
                                               const char* xb, char* sb,
                                               const float2* ps, const float4* d6r,
                                               const uint4* pk) {
        float4 r0 = d6r[2 * j];                         // broadcast LDS.128
        float4 r1 = d6r[2 * j + 1];                     // broadcast LDS.128

        float2 x6 = lds2(xb + __float_as_int(r0.y));
        float e6a = x6.x * r0.x;
        float e6b = x6.y * r0.x;
        float D6a = fmaf(Da, e6a, Da);
        float D6b = fmaf(Db, e6b, Db);
        float NRa = Na * e6a;
        float NRb = Nb * e6b;

        float2 xL = lds2(xb + __float_as_int(r0.w));
        float eLa = xL.x * r0.z;
        float eLb = xL.y * r0.z;
        float DLa = fmaf(D6a, eLa, D6a);
        float DLb = fmaf(D6b, eLb, D6b);

        float2 xR = lds2(xb + __float_as_int(r1.y));
        float eRa = xR.x * r1.x;
        float eRb = xR.y * r1.x;
        float DRa = fmaf(D6a, eRa, D6a);
        float DRb = fmaf(D6b, eRb, D6b);

        float ra  = rcpf(DLa * DRa);
        float rb  = rcpf(DLb * DRb);
        float iLa = ra * DRa, iRa = ra * DLa;
        float iLb = rb * DRb, iRb = rb * DLb;

        float PLLa = Na * iLa,   PLLb = Nb * iLb;       // leaf 4j
        float PLRa = PLLa * eLa, PLRb = PLLb * eLb;     // leaf 4j+1
        float PRLa = NRa * iRa,  PRLb = NRb * iRb;      // leaf 4j+2
        float PRRa = PRLa * eRa, PRRb = PRLb * eRb;     // leaf 4j+3

        uint4 k = pk[j];                                // broadcast LDS.128
        {
            float2* a = (float2*)(sb + k.x);
            float2 v = *a; v.x += PLLa; v.y += PLLb; *a = v;
        }
        {
            float2* a = (float2*)(sb + k.y);
            float2 v = *a; v.x += PLRa; v.y += PLRb; *a = v;
        }
        {
            float2* a = (float2*)(sb + k.z);
            float2 v = *a; v.x += PRLa; v.y += PRLb; *a = v;
        }
        {
            float2* a = (float2*)(sb + k.w);
            float2 v = *a; v.x += PRRa; v.y += PRRb; *a = v;
        }
    }
};

__global__ void __launch_bounds__(BT, 10)
dt_kernel(const float* __restrict__ x,
          const float* __restrict__ thr,
          const int*   __restrict__ feats,
          const int*   __restrict__ cls,
          float* __restrict__ out) {
    __shared__ __align__(16) float    xs[N_FEAT * PADF];      // 8.25 KB: E[f,s]=exp(x)
    __shared__ __align__(16) float    sacc[4 * N_CLS * SPB];  // 10 KB
    __shared__ __align__(8)  float2   s_top[3];
    __shared__ __align__(8)  float2   s_ps[4 * N_INNER];      // 480 B (depths 2..5)
    __shared__ __align__(16) float4   s_d6[64 * 2];           // 2 KB  (d6+d7 params)
    __shared__ __align__(16) uint4    s_pk[64];               // 1 KB  leaf offsets

    const int tid = threadIdx.x;
    const int bs  = blockIdx.x * SPB;
    const int q   = tid >> 5;              // quarter == warp index
    const int pr  = tid & (NPAIR - 1);     // sample-pair index (lane)

    // ---- per-block param prep: node constant c = exp(-t) ----
    if (tid < 3) {
        s_top[tid] = make_float2(ex2f(-thr[tid] * LOG2E),
                                 __int_as_float(feats[tid] * PADF * 4));
    }
    if (tid < 4 * N_INNER) {               // 60 inner params (tree depths 2..5)
        int qq  = tid / N_INNER;
        int rem = tid - qq * N_INNER;      // 0..14, level order
        int ldp = 31 - __clz(rem + 1);     // 0..3
        int j   = rem + 1 - (1 << ldp);
        int g   = ((1 << (ldp + 2)) - 1) + qq * (1 << ldp) + j;
        s_ps[tid] = make_float2(ex2f(-thr[g] * LOG2E),
                                __int_as_float(feats[g] * PADF * 4));
    }
    {                                      // 128 float4 d6 records
        int d6 = tid >> 1;                 // global in-level d6 index 0..63
        int w  = tid & 1;
        if (w == 0) {
            int g6 = 63 + d6;              // depth-6 node
            int gL = 127 + 2 * d6;         // left d7 child
            s_d6[tid] = make_float4(ex2f(-thr[g6] * LOG2E),
                                    __int_as_float(feats[g6] * PADF * 4),
                                    ex2f(-thr[gL] * LOG2E),
                                    __int_as_float(feats[gL] * PADF * 4));
        } else {
            int gR = 128 + 2 * d6;         // right d7 child
            s_d6[tid] = make_float4(ex2f(-thr[gR] * LOG2E),
                                    __int_as_float(feats[gR] * PADF * 4),
                                    0.f, 0.f);
        }
    }
    if (tid < 64) {                        // leaf class byte-offsets per d6
        int lb = tid * 4;
        s_pk[tid] = make_uint4((uint32_t)cls[lb + 0] * (SPB * 4),
                               (uint32_t)cls[lb + 1] * (SPB * 4),
                               (uint32_t)cls[lb + 2] * (SPB * 4),
                               (uint32_t)cls[lb + 3] * (SPB * 4));
    }

    // ---- stage E = exp(x): 64 samples x 32 feats, coalesced LDG.128 + ex2 ----
#pragma unroll
    for (int k = 0; k < (SPB * N_FEAT / 4) / BT; k++) {
        int idx = tid + k * BT;
        int s   = idx >> 3;
        int c4  = idx & 7;
        float4 v = reinterpret_cast<const float4*>(x + (size_t)(bs + s) * N_FEAT)[c4];
        xs[(c4 * 4 + 0) * PADF + s] = ex2f(v.x * LOG2E);
        xs[(c4 * 4 + 1) * PADF + s] = ex2f(v.y * LOG2E);
        xs[(c4 * 4 + 2) * PADF + s] = ex2f(v.z * LOG2E);
        xs[(c4 * 4 + 3) * PADF + s] = ex2f(v.w * LOG2E);
    }

    char* sb = (char*)sacc + q * (N_CLS * SPB * 4) + 8 * pr;
#pragma unroll
    for (int c = 0; c < N_CLS; c++)
        *(float2*)(sb + c * (SPB * 4)) = make_float2(0.f, 0.f);

    __syncthreads();

    const char* xb = (const char*)xs + 8 * pr;
    const float2* ps  = s_ps + q * N_INNER;
    const float4* d6r = s_d6 + q * 32;     // 16 d6 records x2 per quarter
    const uint4*  pk  = s_pk + q * 16;

    // replicated top 2 levels
    float2 p0  = s_top[0];
    float2 xv0 = lds2(xb + __float_as_int(p0.y));
    float e0a = xv0.x * p0.x;
    float e0b = xv0.y * p0.x;
    float Da = e0a + 1.f;
    float Db = e0b + 1.f;
    float Na = (q & 2) ? e0a : 1.0f;
    float Nb = (q & 2) ? e0b : 1.0f;

    float2 p1  = s_top[1 + (q >> 1)];
    float2 xv1 = lds2(xb + __float_as_int(p1.y));
    float e1a = xv1.x * p1.x;
    float e1b = xv1.y * p1.x;
    Da = fmaf(Da, e1a, Da);
    Db = fmaf(Db, e1b, Db);
    if (q & 1) { Na *= e1a; Nb *= e1b; }

    Walk<0, 0>::run(Na, Da, Nb, Db, xb, sb, ps, d6r, pk);

    __syncthreads();

    // combine 4 quarter-accumulators, write out (threads 0..63, one sample each)
    if (tid < SPB) {
        float a[N_CLS];
#pragma unroll
        for (int c = 0; c < N_CLS; c++) {
            float v = 0.f;
#pragma unroll
            for (int qq = 0; qq < 4; qq++)
                v += sacc[qq * (N_CLS * SPB) + c * SPB + tid];
            a[c] = v;
        }
        float* o = out + (size_t)(bs + tid) * N_CLS;
#pragma unroll
        for (int c = 0; c < N_CLS; c += 2)
            *(float2*)(o + c) = make_float2(a[c], a[c + 1]);
    }
}

extern "C" void kernel_launch(void* const* d_in, const int* in_sizes, int n_in,
                              void* d_out, int out_size) {
    const float* x     = (const float*)d_in[0];
    const float* thr   = (const float*)d_in[1];
    const int*   feats = (const int*)d_in[2];
    const int*   cls   = (const int*)d_in[3];
    float*       out   = (float*)d_out;

    const int B = in_sizes[0] / N_FEAT;

    dt_kernel<<<B / SPB, BT>>>(x, thr, feats, cls, out);
}